// round 4
// baseline (speedup 1.0000x reference)
#include <cuda_runtime.h>
#include <cuda_bf16.h>

#define U_N 50000
#define I_N 25000
#define NN  75000
#define DD  64
#define EE  2000000
#define BB  4096

// Scratch (device globals — no runtime allocation allowed)
__device__ float g_buf0[(size_t)NN * DD];
__device__ float g_buf1[(size_t)NN * DD];
__device__ float g_acc [(size_t)NN * DD];
__device__ int   g_cnt [NN];
__device__ int   g_rowptr[NN + 1];
__device__ int   g_woff[NN];
__device__ int   g_colc[EE];
__device__ float g_valc[EE];
__device__ int   g_is64;   // 1 if index buffers are int64, 0 if int32

// Read index i from a buffer whose element type is int32 or int64 (flagged).
__device__ __forceinline__ int ldidx(const void* __restrict__ p, int i, int is64) {
    if (is64) return (int)((const long long*)p)[i];
    return ((const int*)p)[i];
}

// ---------------------------------------------------------------------------
// Detect index dtype: if int64, all odd 32-bit words (high halves) are zero.
// ---------------------------------------------------------------------------
__global__ void detect_kernel(const void* __restrict__ erow) {
    // single warp; scan first 2048 int32 words (safe: buffer >= 8MB either way)
    const int* w = (const int*)erow;
    int lane = threadIdx.x;
    int any_odd_nonzero = 0;
    for (int i = lane; i < 1024; i += 32) {
        if (w[2 * i + 1] != 0) any_odd_nonzero = 1;
    }
    #pragma unroll
    for (int o = 16; o > 0; o >>= 1)
        any_odd_nonzero |= __shfl_xor_sync(0xFFFFFFFFu, any_odd_nonzero, o);
    if (lane == 0) g_is64 = any_odd_nonzero ? 0 : 1;
}

// ---------------------------------------------------------------------------
// Init: acc = cur = concat(emb_user, emb_item); zero histogram counters.
// ---------------------------------------------------------------------------
__global__ void init_kernel(const float* __restrict__ eu, const float* __restrict__ ei) {
    int idx = blockIdx.x * blockDim.x + threadIdx.x;
    const int total = NN * DD;
    if (idx < total) {
        float v = (idx < U_N * DD) ? eu[idx] : ei[idx - U_N * DD];
        g_buf0[idx] = v;
        g_acc[idx]  = v;
    }
    if (idx < NN) g_cnt[idx] = 0;
}

// ---------------------------------------------------------------------------
// CSR build: histogram -> exclusive scan -> scatter
// ---------------------------------------------------------------------------
__global__ void hist_kernel(const void* __restrict__ erow) {
    int i = blockIdx.x * blockDim.x + threadIdx.x;
    int is64 = g_is64;
    if (i < EE) {
        int r = ldidx(erow, i, is64);
        atomicAdd(&g_cnt[r], 1);
    }
}

__global__ void scan_kernel() {
    // single block, 1024 threads, tiled exclusive scan over NN counters
    __shared__ int warp_sums[32];
    int tid  = threadIdx.x;
    int lane = tid & 31;
    int wid  = tid >> 5;
    int carry = 0;
    for (int base = 0; base < NN; base += 1024) {
        int i = base + tid;
        int v = (i < NN) ? g_cnt[i] : 0;
        int x = v;
        #pragma unroll
        for (int o = 1; o < 32; o <<= 1) {
            int y = __shfl_up_sync(0xFFFFFFFFu, x, o);
            if (lane >= o) x += y;
        }
        if (lane == 31) warp_sums[wid] = x;
        __syncthreads();
        if (tid < 32) {
            int w = warp_sums[tid];
            #pragma unroll
            for (int o = 1; o < 32; o <<= 1) {
                int y = __shfl_up_sync(0xFFFFFFFFu, w, o);
                if (tid >= o) w += y;
            }
            warp_sums[tid] = w;
        }
        __syncthreads();
        int excl = x - v + carry + (wid > 0 ? warp_sums[wid - 1] : 0);
        if (i < NN) { g_rowptr[i] = excl; g_woff[i] = excl; }
        int total = warp_sums[31];
        __syncthreads();   // protect warp_sums before next tile (WAR)
        carry += total;
    }
    if (tid == 0) g_rowptr[NN] = carry;
}

__global__ void scatter_kernel(const void* __restrict__ erow,
                               const void* __restrict__ ecol,
                               const float* __restrict__ evals) {
    int i = blockIdx.x * blockDim.x + threadIdx.x;
    int is64 = g_is64;
    if (i < EE) {
        int r = ldidx(erow, i, is64);
        int c = ldidx(ecol, i, is64);
        int pos = atomicAdd(&g_woff[r], 1);
        g_colc[pos] = c;
        g_valc[pos] = evals[i];
    }
}

// ---------------------------------------------------------------------------
// SpMM pass (gather form): one warp per row; also fold acc += next.
// ---------------------------------------------------------------------------
__global__ void spmm_kernel(const float* __restrict__ cur, float* __restrict__ next) {
    int warp = (blockIdx.x * blockDim.x + threadIdx.x) >> 5;
    if (warp >= NN) return;
    int lane = threadIdx.x & 31;
    int s = g_rowptr[warp];
    int e = g_rowptr[warp + 1];
    float2 a = make_float2(0.f, 0.f);
    for (int i = s; i < e; i++) {
        int   c = __ldg(&g_colc[i]);
        float v = __ldg(&g_valc[i]);
        float2 xv = *(const float2*)(cur + (size_t)c * DD + lane * 2);
        a.x = fmaf(v, xv.x, a.x);
        a.y = fmaf(v, xv.y, a.y);
    }
    size_t o = (size_t)warp * DD + lane * 2;
    *(float2*)(next + o) = a;
    float2 av = *(float2*)(g_acc + o);
    av.x += a.x; av.y += a.y;
    *(float2*)(g_acc + o) = av;
}

// ---------------------------------------------------------------------------
// Epilogue: gather light_out (= acc/4), two 64x64 GEMVs, softmax/sigmoid/dot.
// One warp per batch element; W kept transposed in smem (conflict-free LDS).
// ---------------------------------------------------------------------------
__global__ void final_kernel(const float* __restrict__ xij0, const float* __restrict__ xij1,
                             const float* __restrict__ wu,   const float* __restrict__ wi,
                             const void* __restrict__ users,
                             const void* __restrict__ items,
                             const int* __restrict__ xij,
                             float* __restrict__ out) {
    __shared__ float swu[DD * DD];   // swu[d*64 + j] = wu[j*64 + d]
    __shared__ float swi[DD * DD];
    __shared__ float svec[8][2 * DD];

    int tid = threadIdx.x;
    for (int k = tid; k < DD * DD; k += blockDim.x) {
        int j = k / DD, d = k % DD;
        swu[d * DD + j] = wu[k];
        swi[d * DD + j] = wi[k];
    }
    __syncthreads();

    int warp = tid >> 5, lane = tid & 31;
    int b = blockIdx.x * (blockDim.x >> 5) + warp;
    if (b >= BB) return;

    int is64 = g_is64;
    int uu = ldidx(users, b, is64);
    int ii = ldidx(items, b, is64);

    float* uv = svec[warp];
    float* iv = svec[warp] + DD;
    uv[lane]      = g_acc[(size_t)uu * DD + lane]        * 0.25f;
    uv[lane + 32] = g_acc[(size_t)uu * DD + lane + 32]   * 0.25f;
    iv[lane]      = g_acc[(size_t)(U_N + ii) * DD + lane]      * 0.25f;
    iv[lane + 32] = g_acc[(size_t)(U_N + ii) * DD + lane + 32] * 0.25f;
    __syncwarp();

    int j0 = lane, j1 = lane + 32;
    float su0 = 0.f, su1 = 0.f, si0 = 0.f, si1 = 0.f;
    #pragma unroll
    for (int d = 0; d < DD; d++) {
        float ud = uv[d];
        float id = iv[d];
        su0 = fmaf(ud, swu[d * DD + j0], su0);
        su1 = fmaf(ud, swu[d * DD + j1], su1);
        si0 = fmaf(id, swi[d * DD + j0], si0);
        si1 = fmaf(id, swi[d * DD + j1], si1);
    }

    // softmax over the 64 user logits held 2-per-lane
    float m = fmaxf(su0, su1);
    #pragma unroll
    for (int o = 16; o > 0; o >>= 1) m = fmaxf(m, __shfl_xor_sync(0xFFFFFFFFu, m, o));
    float e0 = expf(su0 - m), e1 = expf(su1 - m);
    float ssum = e0 + e1;
    #pragma unroll
    for (int o = 16; o > 0; o >>= 1) ssum += __shfl_xor_sync(0xFFFFFFFFu, ssum, o);
    float scale = 0.5f / ssum;   // (1 - HYPER_X) / sum

    float sg0 = 1.f / (1.f + expf(-si0));
    float sg1 = 1.f / (1.f + expf(-si1));
    float part = e0 * scale * sg0 + e1 * scale * sg1;
    #pragma unroll
    for (int o = 16; o > 0; o >>= 1) part += __shfl_xor_sync(0xFFFFFFFFu, part, o);

    if (lane == 0) {
        float xe = xij[b] ? xij1[ii] : xij0[ii];
        float sgx = 1.f / (1.f + expf(-xe));
        out[b] = part + 0.5f * sgx;
    }
}

// ---------------------------------------------------------------------------
extern "C" void kernel_launch(void* const* d_in, const int* in_sizes, int n_in,
                              void* d_out, int out_size) {
    const float* emb_user  = (const float*)d_in[0];
    const float* emb_item  = (const float*)d_in[1];
    const float* xij0      = (const float*)d_in[2];
    const float* xij1      = (const float*)d_in[3];
    const float* w_user    = (const float*)d_in[4];
    const float* w_item    = (const float*)d_in[5];
    const float* edge_vals = (const float*)d_in[6];
    const void*  edge_row  = d_in[7];
    const void*  edge_col  = d_in[8];
    const void*  users     = d_in[9];
    const void*  items     = d_in[10];
    const int*   xij       = (const int*)d_in[11];
    float* out = (float*)d_out;

    float *b0, *b1;
    cudaGetSymbolAddress((void**)&b0, g_buf0);
    cudaGetSymbolAddress((void**)&b1, g_buf1);

    detect_kernel<<<1, 32>>>(edge_row);
    init_kernel<<<(NN * DD + 255) / 256, 256>>>(emb_user, emb_item);
    hist_kernel<<<(EE + 255) / 256, 256>>>(edge_row);
    scan_kernel<<<1, 1024>>>();
    scatter_kernel<<<(EE + 255) / 256, 256>>>(edge_row, edge_col, edge_vals);

    const int warps_per_block = 8;
    const int spmm_blocks = (NN + warps_per_block - 1) / warps_per_block;
    spmm_kernel<<<spmm_blocks, 256>>>(b0, b1);
    spmm_kernel<<<spmm_blocks, 256>>>(b1, b0);
    spmm_kernel<<<spmm_blocks, 256>>>(b0, b1);

    final_kernel<<<BB / 8, 256>>>(xij0, xij1, w_user, w_item, users, items, xij, out);
}

// round 8
// speedup vs baseline: 1.2207x; 1.2207x over previous
#include <cuda_runtime.h>
#include <cuda_bf16.h>

#define U_N 50000
#define I_N 25000
#define NN  75000
#define DD  64
#define EE  2000000
#define BB  4096
#define SCAN_BLK 1024
#define NBLKS ((NN + SCAN_BLK - 1) / SCAN_BLK)   // 74

// Scratch (device globals — no runtime allocation allowed)
__device__ float g_buf0[(size_t)NN * DD];   // x0
__device__ float g_buf1[(size_t)NN * DD];   // x1
__device__ float g_buf2[(size_t)NN * DD];   // x2
__device__ float g_buf3[(size_t)NN * DD];   // x3
__device__ int   g_cnt [NN];
__device__ int   g_rowptr[NN + 1];
__device__ int   g_woff[NN];
__device__ int2  g_edge[EE];                // (col, val-as-int)
__device__ int   g_bsum[NBLKS];
__device__ int   g_boff[NBLKS];
__device__ int   g_is64;   // 1 if index buffers are int64, 0 if int32

__device__ __forceinline__ int ldidx(const void* __restrict__ p, int i, int is64) {
    if (is64) return (int)((const long long*)p)[i];
    return ((const int*)p)[i];
}

// ---------------------------------------------------------------------------
// Detect index dtype: if int64, all odd 32-bit words (high halves) are zero.
// ---------------------------------------------------------------------------
__global__ void detect_kernel(const void* __restrict__ erow) {
    const int* w = (const int*)erow;
    int lane = threadIdx.x;
    int any_odd_nonzero = 0;
    for (int i = lane; i < 1024; i += 32)
        if (w[2 * i + 1] != 0) any_odd_nonzero = 1;
    #pragma unroll
    for (int o = 16; o > 0; o >>= 1)
        any_odd_nonzero |= __shfl_xor_sync(0xFFFFFFFFu, any_odd_nonzero, o);
    if (lane == 0) g_is64 = any_odd_nonzero ? 0 : 1;
}

// ---------------------------------------------------------------------------
// Init: x0 = concat(emb_user, emb_item); zero histogram counters.
// ---------------------------------------------------------------------------
__global__ void init_kernel(const float* __restrict__ eu, const float* __restrict__ ei) {
    int idx = blockIdx.x * blockDim.x + threadIdx.x;
    const int total = NN * DD;
    if (idx < total)
        g_buf0[idx] = (idx < U_N * DD) ? eu[idx] : ei[idx - U_N * DD];
    if (idx < NN) g_cnt[idx] = 0;
    if (idx == 0) g_rowptr[NN] = EE;   // total is EE by construction
}

// ---------------------------------------------------------------------------
// CSR build: histogram -> parallel 3-stage scan -> scatter
// ---------------------------------------------------------------------------
__global__ void hist_kernel(const void* __restrict__ erow) {
    int i = blockIdx.x * blockDim.x + threadIdx.x;
    int is64 = g_is64;
    if (i < EE) atomicAdd(&g_cnt[ldidx(erow, i, is64)], 1);
}

// Stage 1: per-block exclusive scan; block totals to g_bsum.
__global__ void scan1_kernel() {
    __shared__ int warp_sums[32];
    int tid  = threadIdx.x;
    int lane = tid & 31;
    int wid  = tid >> 5;
    int i = blockIdx.x * SCAN_BLK + tid;
    int v = (i < NN) ? g_cnt[i] : 0;
    int x = v;
    #pragma unroll
    for (int o = 1; o < 32; o <<= 1) {
        int y = __shfl_up_sync(0xFFFFFFFFu, x, o);
        if (lane >= o) x += y;
    }
    if (lane == 31) warp_sums[wid] = x;
    __syncthreads();
    if (tid < 32) {
        int w = warp_sums[tid];
        #pragma unroll
        for (int o = 1; o < 32; o <<= 1) {
            int y = __shfl_up_sync(0xFFFFFFFFu, w, o);
            if (tid >= o) w += y;
        }
        warp_sums[tid] = w;
    }
    __syncthreads();
    int excl = x - v + (wid > 0 ? warp_sums[wid - 1] : 0);
    if (i < NN) g_rowptr[i] = excl;               // local (per-block) offsets
    if (tid == SCAN_BLK - 1) g_bsum[blockIdx.x] = excl + v;
}

// Stage 2: exclusive scan of the NBLKS block totals (single block, 128 thr).
__global__ void scan2_kernel() {
    __shared__ int ws[4];
    int tid = threadIdx.x, lane = tid & 31, wid = tid >> 5;
    int v = (tid < NBLKS) ? g_bsum[tid] : 0;
    int x = v;
    #pragma unroll
    for (int o = 1; o < 32; o <<= 1) {
        int y = __shfl_up_sync(0xFFFFFFFFu, x, o);
        if (lane >= o) x += y;
    }
    if (lane == 31) ws[wid] = x;
    __syncthreads();
    if (tid == 0) {
        int s = 0;
        #pragma unroll
        for (int k = 0; k < 4; k++) { int t = ws[k]; ws[k] = s; s += t; }
    }
    __syncthreads();
    if (tid < NBLKS) g_boff[tid] = x - v + ws[wid];
}

// Stage 3: add block offsets; produce final rowptr + write cursor.
__global__ void scan3_kernel() {
    int i = blockIdx.x * SCAN_BLK + threadIdx.x;
    if (i < NN) {
        int r = g_rowptr[i] + g_boff[blockIdx.x];
        g_rowptr[i] = r;
        g_woff[i]   = r;
    }
}

__global__ void scatter_kernel(const void* __restrict__ erow,
                               const void* __restrict__ ecol,
                               const float* __restrict__ evals) {
    int i = blockIdx.x * blockDim.x + threadIdx.x;
    int is64 = g_is64;
    if (i < EE) {
        int r = ldidx(erow, i, is64);
        int c = ldidx(ecol, i, is64);
        int pos = atomicAdd(&g_woff[r], 1);
        g_edge[pos] = make_int2(c, __float_as_int(evals[i]));
    }
}

// ---------------------------------------------------------------------------
// SpMM pass (gather form): one warp per row. next[row] = sum val * cur[col].
// ---------------------------------------------------------------------------
__global__ void spmm_kernel(const float* __restrict__ cur, float* __restrict__ next) {
    int warp = (blockIdx.x * blockDim.x + threadIdx.x) >> 5;
    if (warp >= NN) return;
    int lane = threadIdx.x & 31;
    int s = g_rowptr[warp];
    int e = g_rowptr[warp + 1];
    float2 a = make_float2(0.f, 0.f);
    for (int i = s; i < e; i++) {
        int2 ev = __ldg(&g_edge[i]);
        float v = __int_as_float(ev.y);
        float2 xv = *(const float2*)(cur + (size_t)ev.x * DD + lane * 2);
        a.x = fmaf(v, xv.x, a.x);
        a.y = fmaf(v, xv.y, a.y);
    }
    *(float2*)(next + (size_t)warp * DD + lane * 2) = a;
}

// ---------------------------------------------------------------------------
// Epilogue: light_out = (x0+x1+x2+x3)/4 gathered at sampled rows,
// two 64x64 GEMVs, softmax/sigmoid/dot. One warp per batch element.
// ---------------------------------------------------------------------------
__global__ void final_kernel(const float* __restrict__ xij0, const float* __restrict__ xij1,
                             const float* __restrict__ wu,   const float* __restrict__ wi,
                             const void* __restrict__ users,
                             const void* __restrict__ items,
                             const int* __restrict__ xij,
                             float* __restrict__ out) {
    __shared__ float swu[DD * DD];   // swu[d*64 + j] = wu[j*64 + d]
    __shared__ float swi[DD * DD];
    __shared__ float svec[8][2 * DD];

    int tid = threadIdx.x;
    for (int k = tid; k < DD * DD; k += blockDim.x) {
        int j = k / DD, d = k % DD;
        swu[d * DD + j] = wu[k];
        swi[d * DD + j] = wi[k];
    }
    __syncthreads();

    int warp = tid >> 5, lane = tid & 31;
    int b = blockIdx.x * (blockDim.x >> 5) + warp;
    if (b >= BB) return;

    int is64 = g_is64;
    int uu = ldidx(users, b, is64);
    int ii = ldidx(items, b, is64);

    size_t ou = (size_t)uu * DD;
    size_t oi = (size_t)(U_N + ii) * DD;

    float* uv = svec[warp];
    float* iv = svec[warp] + DD;
    #pragma unroll
    for (int h = 0; h < 2; h++) {
        int d = lane + 32 * h;
        uv[d] = (g_buf0[ou + d] + g_buf1[ou + d] + g_buf2[ou + d] + g_buf3[ou + d]) * 0.25f;
        iv[d] = (g_buf0[oi + d] + g_buf1[oi + d] + g_buf2[oi + d] + g_buf3[oi + d]) * 0.25f;
    }
    __syncwarp();

    int j0 = lane, j1 = lane + 32;
    float su0 = 0.f, su1 = 0.f, si0 = 0.f, si1 = 0.f;
    #pragma unroll
    for (int d = 0; d < DD; d++) {
        float ud = uv[d];
        float id = iv[d];
        su0 = fmaf(ud, swu[d * DD + j0], su0);
        su1 = fmaf(ud, swu[d * DD + j1], su1);
        si0 = fmaf(id, swi[d * DD + j0], si0);
        si1 = fmaf(id, swi[d * DD + j1], si1);
    }

    float m = fmaxf(su0, su1);
    #pragma unroll
    for (int o = 16; o > 0; o >>= 1) m = fmaxf(m, __shfl_xor_sync(0xFFFFFFFFu, m, o));
    float e0 = expf(su0 - m), e1 = expf(su1 - m);
    float ssum = e0 + e1;
    #pragma unroll
    for (int o = 16; o > 0; o >>= 1) ssum += __shfl_xor_sync(0xFFFFFFFFu, ssum, o);
    float scale = 0.5f / ssum;   // (1 - HYPER_X) / sum

    float sg0 = 1.f / (1.f + expf(-si0));
    float sg1 = 1.f / (1.f + expf(-si1));
    float part = e0 * scale * sg0 + e1 * scale * sg1;
    #pragma unroll
    for (int o = 16; o > 0; o >>= 1) part += __shfl_xor_sync(0xFFFFFFFFu, part, o);

    if (lane == 0) {
        float xe = xij[b] ? xij1[ii] : xij0[ii];
        float sgx = 1.f / (1.f + expf(-xe));
        out[b] = part + 0.5f * sgx;
    }
}

// ---------------------------------------------------------------------------
extern "C" void kernel_launch(void* const* d_in, const int* in_sizes, int n_in,
                              void* d_out, int out_size) {
    const float* emb_user  = (const float*)d_in[0];
    const float* emb_item  = (const float*)d_in[1];
    const float* xij0      = (const float*)d_in[2];
    const float* xij1      = (const float*)d_in[3];
    const float* w_user    = (const float*)d_in[4];
    const float* w_item    = (const float*)d_in[5];
    const float* edge_vals = (const float*)d_in[6];
    const void*  edge_row  = d_in[7];
    const void*  edge_col  = d_in[8];
    const void*  users     = d_in[9];
    const void*  items     = d_in[10];
    const int*   xij       = (const int*)d_in[11];
    float* out = (float*)d_out;

    float *b0, *b1, *b2, *b3;
    cudaGetSymbolAddress((void**)&b0, g_buf0);
    cudaGetSymbolAddress((void**)&b1, g_buf1);
    cudaGetSymbolAddress((void**)&b2, g_buf2);
    cudaGetSymbolAddress((void**)&b3, g_buf3);

    detect_kernel<<<1, 32>>>(edge_row);
    init_kernel<<<(NN * DD + 255) / 256, 256>>>(emb_user, emb_item);
    hist_kernel<<<(EE + 255) / 256, 256>>>(edge_row);
    scan1_kernel<<<NBLKS, SCAN_BLK>>>();
    scan2_kernel<<<1, 128>>>();
    scan3_kernel<<<NBLKS, SCAN_BLK>>>();
    scatter_kernel<<<(EE + 255) / 256, 256>>>(edge_row, edge_col, edge_vals);

    const int warps_per_block = 8;
    const int spmm_blocks = (NN + warps_per_block - 1) / warps_per_block;
    spmm_kernel<<<spmm_blocks, 256>>>(b0, b1);
    spmm_kernel<<<spmm_blocks, 256>>>(b1, b2);
    spmm_kernel<<<spmm_blocks, 256>>>(b2, b3);

    final_kernel<<<BB / 8, 256>>>(xij0, xij1, w_user, w_item, users, items, xij, out);
}

// round 9
// speedup vs baseline: 1.2661x; 1.0372x over previous
#include <cuda_runtime.h>
#include <cuda_fp16.h>

#define U_N 50000
#define I_N 25000
#define NN  75000
#define DD  64
#define HD  (DD / 2)          // half2 per row = 32
#define EE  2000000
#define BB  4096
#define SCAN_BLK 1024
#define NBLKS ((NN + SCAN_BLK - 1) / SCAN_BLK)   // 74

// Scratch (device globals — no runtime allocation allowed)
__device__ __half2 g_h0[(size_t)NN * HD];   // x0 (fp16)
__device__ __half2 g_h1[(size_t)NN * HD];   // x1
__device__ __half2 g_h2[(size_t)NN * HD];   // x2
__device__ __half2 g_h3[(size_t)NN * HD];   // x3
__device__ int   g_cnt [NN];
__device__ int   g_rowptr[NN + 1];
__device__ int   g_woff[NN];
__device__ int2  g_edge[EE];                // (col, val-as-int)
__device__ int   g_bsum[NBLKS];
__device__ int   g_boff[NBLKS];
__device__ int   g_is64;   // 1 if index buffers are int64, 0 if int32

__device__ __forceinline__ int ldidx(const void* __restrict__ p, int i, int is64) {
    if (is64) return (int)((const long long*)p)[i];
    return ((const int*)p)[i];
}

// ---------------------------------------------------------------------------
// Detect index dtype: if int64, all odd 32-bit words (high halves) are zero.
// ---------------------------------------------------------------------------
__global__ void detect_kernel(const void* __restrict__ erow) {
    const int* w = (const int*)erow;
    int lane = threadIdx.x;
    int any_odd_nonzero = 0;
    for (int i = lane; i < 1024; i += 32)
        if (w[2 * i + 1] != 0) any_odd_nonzero = 1;
    #pragma unroll
    for (int o = 16; o > 0; o >>= 1)
        any_odd_nonzero |= __shfl_xor_sync(0xFFFFFFFFu, any_odd_nonzero, o);
    if (lane == 0) g_is64 = any_odd_nonzero ? 0 : 1;
}

// ---------------------------------------------------------------------------
// Init: x0 = fp16(concat(emb_user, emb_item)); zero histogram counters.
// ---------------------------------------------------------------------------
__global__ void init_kernel(const float* __restrict__ eu, const float* __restrict__ ei) {
    int idx = blockIdx.x * blockDim.x + threadIdx.x;   // one half2 = 2 floats
    const int total = NN * HD;
    if (idx < total) {
        int fidx = idx * 2;
        float2 v;
        if (fidx < U_N * DD) {
            v = *(const float2*)(eu + fidx);
        } else {
            v = *(const float2*)(ei + (fidx - U_N * DD));
        }
        g_h0[idx] = __float22half2_rn(v);
    }
    if (idx < NN) g_cnt[idx] = 0;
    if (idx == 0) g_rowptr[NN] = EE;
}

// ---------------------------------------------------------------------------
// CSR build: histogram -> parallel 3-stage scan -> scatter
// ---------------------------------------------------------------------------
__global__ void hist_kernel(const void* __restrict__ erow) {
    int i = blockIdx.x * blockDim.x + threadIdx.x;
    int is64 = g_is64;
    if (i < EE) atomicAdd(&g_cnt[ldidx(erow, i, is64)], 1);
}

__global__ void scan1_kernel() {
    __shared__ int warp_sums[32];
    int tid  = threadIdx.x;
    int lane = tid & 31;
    int wid  = tid >> 5;
    int i = blockIdx.x * SCAN_BLK + tid;
    int v = (i < NN) ? g_cnt[i] : 0;
    int x = v;
    #pragma unroll
    for (int o = 1; o < 32; o <<= 1) {
        int y = __shfl_up_sync(0xFFFFFFFFu, x, o);
        if (lane >= o) x += y;
    }
    if (lane == 31) warp_sums[wid] = x;
    __syncthreads();
    if (tid < 32) {
        int w = warp_sums[tid];
        #pragma unroll
        for (int o = 1; o < 32; o <<= 1) {
            int y = __shfl_up_sync(0xFFFFFFFFu, w, o);
            if (tid >= o) w += y;
        }
        warp_sums[tid] = w;
    }
    __syncthreads();
    int excl = x - v + (wid > 0 ? warp_sums[wid - 1] : 0);
    if (i < NN) g_rowptr[i] = excl;
    if (tid == SCAN_BLK - 1) g_bsum[blockIdx.x] = excl + v;
}

__global__ void scan2_kernel() {
    __shared__ int ws[4];
    int tid = threadIdx.x, lane = tid & 31, wid = tid >> 5;
    int v = (tid < NBLKS) ? g_bsum[tid] : 0;
    int x = v;
    #pragma unroll
    for (int o = 1; o < 32; o <<= 1) {
        int y = __shfl_up_sync(0xFFFFFFFFu, x, o);
        if (lane >= o) x += y;
    }
    if (lane == 31) ws[wid] = x;
    __syncthreads();
    if (tid == 0) {
        int s = 0;
        #pragma unroll
        for (int k = 0; k < 4; k++) { int t = ws[k]; ws[k] = s; s += t; }
    }
    __syncthreads();
    if (tid < NBLKS) g_boff[tid] = x - v + ws[wid];
}

__global__ void scan3_kernel() {
    int i = blockIdx.x * SCAN_BLK + threadIdx.x;
    if (i < NN) {
        int r = g_rowptr[i] + g_boff[blockIdx.x];
        g_rowptr[i] = r;
        g_woff[i]   = r;
    }
}

__global__ void scatter_kernel(const void* __restrict__ erow,
                               const void* __restrict__ ecol,
                               const float* __restrict__ evals) {
    int i = blockIdx.x * blockDim.x + threadIdx.x;
    int is64 = g_is64;
    if (i < EE) {
        int r = ldidx(erow, i, is64);
        int c = ldidx(ecol, i, is64);
        int pos = atomicAdd(&g_woff[r], 1);
        g_edge[pos] = make_int2(c, __float_as_int(evals[i]));
    }
}

// ---------------------------------------------------------------------------
// SpMM pass (gather form): one warp per row; fp16 storage, fp32 accumulate.
// Each lane covers 2 feature dims via one half2 (4B) load -> 128B/row gather.
// ---------------------------------------------------------------------------
__global__ void spmm_kernel(const __half2* __restrict__ cur, __half2* __restrict__ next) {
    int warp = (blockIdx.x * blockDim.x + threadIdx.x) >> 5;
    if (warp >= NN) return;
    int lane = threadIdx.x & 31;
    int s = g_rowptr[warp];
    int e = g_rowptr[warp + 1];
    float2 a = make_float2(0.f, 0.f);
    for (int i = s; i < e; i++) {
        int2 ev = __ldg(&g_edge[i]);
        float v = __int_as_float(ev.y);
        float2 xv = __half22float2(__ldg(&cur[(size_t)ev.x * HD + lane]));
        a.x = fmaf(v, xv.x, a.x);
        a.y = fmaf(v, xv.y, a.y);
    }
    next[(size_t)warp * HD + lane] = __float22half2_rn(a);
}

// ---------------------------------------------------------------------------
// Epilogue: light_out = (x0+x1+x2+x3)/4 gathered at sampled rows,
// two 64x64 GEMVs, softmax/sigmoid/dot. One warp per batch element.
// ---------------------------------------------------------------------------
__global__ void final_kernel(const float* __restrict__ xij0, const float* __restrict__ xij1,
                             const float* __restrict__ wu,   const float* __restrict__ wi,
                             const void* __restrict__ users,
                             const void* __restrict__ items,
                             const int* __restrict__ xij,
                             float* __restrict__ out) {
    __shared__ float swu[DD * DD];   // swu[d*64 + j] = wu[j*64 + d]
    __shared__ float swi[DD * DD];
    __shared__ float svec[8][2 * DD];

    int tid = threadIdx.x;
    for (int k = tid; k < DD * DD; k += blockDim.x) {
        int j = k / DD, d = k % DD;
        swu[d * DD + j] = wu[k];
        swi[d * DD + j] = wi[k];
    }
    __syncthreads();

    int warp = tid >> 5, lane = tid & 31;
    int b = blockIdx.x * (blockDim.x >> 5) + warp;
    if (b >= BB) return;

    int is64 = g_is64;
    int uu = ldidx(users, b, is64);
    int ii = ldidx(items, b, is64);

    size_t ou = (size_t)uu * HD + lane;          // half2 index
    size_t oi = (size_t)(U_N + ii) * HD + lane;

    float* uv = svec[warp];
    float* iv = svec[warp] + DD;
    {
        float2 s0 = __half22float2(g_h0[ou]);
        float2 s1 = __half22float2(g_h1[ou]);
        float2 s2 = __half22float2(g_h2[ou]);
        float2 s3 = __half22float2(g_h3[ou]);
        uv[lane * 2]     = (s0.x + s1.x + s2.x + s3.x) * 0.25f;
        uv[lane * 2 + 1] = (s0.y + s1.y + s2.y + s3.y) * 0.25f;
        float2 t0 = __half22float2(g_h0[oi]);
        float2 t1 = __half22float2(g_h1[oi]);
        float2 t2 = __half22float2(g_h2[oi]);
        float2 t3 = __half22float2(g_h3[oi]);
        iv[lane * 2]     = (t0.x + t1.x + t2.x + t3.x) * 0.25f;
        iv[lane * 2 + 1] = (t0.y + t1.y + t2.y + t3.y) * 0.25f;
    }
    __syncwarp();

    int j0 = lane, j1 = lane + 32;
    float su0 = 0.f, su1 = 0.f, si0 = 0.f, si1 = 0.f;
    #pragma unroll
    for (int d = 0; d < DD; d++) {
        float ud = uv[d];
        float id = iv[d];
        su0 = fmaf(ud, swu[d * DD + j0], su0);
        su1 = fmaf(ud, swu[d * DD + j1], su1);
        si0 = fmaf(id, swi[d * DD + j0], si0);
        si1 = fmaf(id, swi[d * DD + j1], si1);
    }

    float m = fmaxf(su0, su1);
    #pragma unroll
    for (int o = 16; o > 0; o >>= 1) m = fmaxf(m, __shfl_xor_sync(0xFFFFFFFFu, m, o));
    float e0 = expf(su0 - m), e1 = expf(su1 - m);
    float ssum = e0 + e1;
    #pragma unroll
    for (int o = 16; o > 0; o >>= 1) ssum += __shfl_xor_sync(0xFFFFFFFFu, ssum, o);
    float scale = 0.5f / ssum;   // (1 - HYPER_X) / sum

    float sg0 = 1.f / (1.f + expf(-si0));
    float sg1 = 1.f / (1.f + expf(-si1));
    float part = e0 * scale * sg0 + e1 * scale * sg1;
    #pragma unroll
    for (int o = 16; o > 0; o >>= 1) part += __shfl_xor_sync(0xFFFFFFFFu, part, o);

    if (lane == 0) {
        float xe = xij[b] ? xij1[ii] : xij0[ii];
        float sgx = 1.f / (1.f + expf(-xe));
        out[b] = part + 0.5f * sgx;
    }
}

// ---------------------------------------------------------------------------
extern "C" void kernel_launch(void* const* d_in, const int* in_sizes, int n_in,
                              void* d_out, int out_size) {
    const float* emb_user  = (const float*)d_in[0];
    const float* emb_item  = (const float*)d_in[1];
    const float* xij0      = (const float*)d_in[2];
    const float* xij1      = (const float*)d_in[3];
    const float* w_user    = (const float*)d_in[4];
    const float* w_item    = (const float*)d_in[5];
    const float* edge_vals = (const float*)d_in[6];
    const void*  edge_row  = d_in[7];
    const void*  edge_col  = d_in[8];
    const void*  users     = d_in[9];
    const void*  items     = d_in[10];
    const int*   xij       = (const int*)d_in[11];
    float* out = (float*)d_out;

    __half2 *h0, *h1, *h2, *h3;
    cudaGetSymbolAddress((void**)&h0, g_h0);
    cudaGetSymbolAddress((void**)&h1, g_h1);
    cudaGetSymbolAddress((void**)&h2, g_h2);
    cudaGetSymbolAddress((void**)&h3, g_h3);

    detect_kernel<<<1, 32>>>(edge_row);
    init_kernel<<<(NN * HD + 255) / 256, 256>>>(emb_user, emb_item);
    hist_kernel<<<(EE + 255) / 256, 256>>>(edge_row);
    scan1_kernel<<<NBLKS, SCAN_BLK>>>();
    scan2_kernel<<<1, 128>>>();
    scan3_kernel<<<NBLKS, SCAN_BLK>>>();
    scatter_kernel<<<(EE + 255) / 256, 256>>>(edge_row, edge_col, edge_vals);

    const int warps_per_block = 8;
    const int spmm_blocks = (NN + warps_per_block - 1) / warps_per_block;
    spmm_kernel<<<spmm_blocks, 256>>>(h0, h1);
    spmm_kernel<<<spmm_blocks, 256>>>(h1, h2);
    spmm_kernel<<<spmm_blocks, 256>>>(h2, h3);

    final_kernel<<<BB / 8, 256>>>(xij0, xij1, w_user, w_item, users, items, xij, out);
}